// round 14
// baseline (speedup 1.0000x reference)
#include <cuda_runtime.h>
#include <cuda_bf16.h>
#include <cstdint>

#define D 64
#define MAX_NODES 100000
#define MAX_EDGES 1600000
#define NBMAXB 800        // max coarse buckets (128 nodes each)
#define EB 8192           // edges per partition block
#define NBS 200           // max partition blocks (1.6M/8192 = 196)
#define ECAP 4096         // smem edge cap per bucket (mean 2048, sigma ~45)

// scratch (no cudaMalloc allowed); all fully overwritten each call
__device__ __align__(16) __nv_bfloat16 g_nbr[(size_t)MAX_NODES * D];
__device__ __align__(16) __nv_bfloat16 g_embh[(size_t)MAX_NODES * D];
__device__ int g_H[NBMAXB * NBS];          // per (bucket, block) counts
__device__ int g_BB[NBMAXB * NBS];         // global offsets per (bucket, block)
__device__ int g_gbase[NBMAXB + 1];        // bucket bases (exclusive)
__device__ unsigned g_part[MAX_EDGES];     // packed src*128 + (dst&127)

static __device__ __forceinline__ uint32_t pack_bf2(float a, float b) {
    uint32_t r;
    asm("cvt.rn.bf16x2.f32 %0, %1, %2;" : "=r"(r) : "f"(b), "f"(a));  // lo=a, hi=b
    return r;
}
#define ADD_BF16X2(acc, v) \
    asm("add.rn.bf16x2 %0, %0, %1;" : "+r"(acc) : "r"(v))

// ---------------------------------------------------------------------------
// K0 prep: emb fp32 -> bf16, zero d_out. (No g_nbr zeroing needed.)
// ---------------------------------------------------------------------------
__global__ __launch_bounds__(256) void prep_kernel(const float* __restrict__ emb,
                                                   float* __restrict__ out,
                                                   int n_grp) {
    int i = blockIdx.x * blockDim.x + threadIdx.x;
    if (i < n_grp) {
        float4 v = __ldg(reinterpret_cast<const float4*>(emb) + i);
        uint2 pk;
        pk.x = pack_bf2(v.x, v.y);
        pk.y = pack_bf2(v.z, v.w);
        reinterpret_cast<uint2*>(g_embh)[i] = pk;
    }
    if (i < D / 4) reinterpret_cast<float4*>(out)[i] = make_float4(0.f, 0.f, 0.f, 0.f);
}

// ---------------------------------------------------------------------------
// K1 bucket-hist: per-block smem histogram over coarse buckets (dst>>7).
// ---------------------------------------------------------------------------
__global__ __launch_bounds__(256) void bhist_kernel(const int* __restrict__ dst,
                                                    int n_edges, int nbuckets) {
    __shared__ int h[NBMAXB];
    const int b = blockIdx.x, t = threadIdx.x;
    for (int i = t; i < nbuckets; i += 256) h[i] = 0;
    __syncthreads();
    const int e0 = b * EB;
    const int e1 = min(e0 + EB, n_edges);
    for (int e = e0 + t; e < e1; e += 256)
        atomicAdd(&h[__ldg(dst + e) >> 7], 1);
    __syncthreads();
    for (int i = t; i < nbuckets; i += 256) g_H[i * NBS + b] = h[i];
}

// ---------------------------------------------------------------------------
// K2 matrix scan (one block, 1024 threads): bucket totals -> exclusive bucket
// bases g_gbase, and per-(bucket, block) global offsets g_BB.
// ---------------------------------------------------------------------------
__global__ __launch_bounds__(1024) void bscan_kernel(int nbuckets, int nb) {
    __shared__ int s[1024];
    const int t = threadIdx.x;
    int tot = 0;
    if (t < nbuckets) {
        const int* row = g_H + t * NBS;
        int b = 0;
        for (; b + 4 <= nb; b += 4)
            tot += row[b] + row[b + 1] + row[b + 2] + row[b + 3];
        for (; b < nb; b++) tot += row[b];
    }
    s[t] = (t < nbuckets) ? tot : 0;
    __syncthreads();
    for (int off = 1; off < 1024; off <<= 1) {
        int v = (t >= off) ? s[t - off] : 0;
        __syncthreads();
        s[t] += v;
        __syncthreads();
    }
    if (t < nbuckets) {
        int run = s[t] - tot;   // exclusive base
        g_gbase[t] = run;
        const int* row = g_H + t * NBS;
        int* brow = g_BB + t * NBS;
        for (int b = 0; b < nb; b++) {
            brow[b] = run;
            run += row[b];
        }
    }
    if (t == 0) g_gbase[nbuckets] = s[1023];
}

// ---------------------------------------------------------------------------
// K3 place (PROFILED): rank edges with SMEM cursors (no global atomics),
// write packed (src*128 | dst&127) into the (bucket, block) region.
// ---------------------------------------------------------------------------
__global__ __launch_bounds__(256) void place_kernel(const int* __restrict__ src,
                                                    const int* __restrict__ dst,
                                                    int n_edges) {
    __shared__ int cur[NBMAXB];
    const int b = blockIdx.x, t = threadIdx.x;
    for (int i = t; i < NBMAXB; i += 256) cur[i] = 0;
    __syncthreads();
    const int e0 = b * EB;
    const int e1 = min(e0 + EB, n_edges);
    for (int e = e0 + t; e < e1; e += 256) {
        int d = __ldg(dst + e);
        int s = __ldg(src + e);
        int k = d >> 7;
        int r = atomicAdd(&cur[k], 1);
        int pos = __ldg(&g_BB[k * NBS + b]) + r;
        g_part[pos] = ((unsigned)s << 7) | (unsigned)(d & 127);
    }
}

// ---------------------------------------------------------------------------
// K4 sort-gather: one CTA per bucket (128 nodes). Counting-sort the bucket's
// edges by dst&127 in smem, then warp-per-dst accumulates emb rows with
// packed bf16x2 adds (1 instr / 4 dims) and writes nbr coalesced.
// ---------------------------------------------------------------------------
__global__ __launch_bounds__(256) void sgather_kernel(int n_nodes) {
    __shared__ unsigned raw[ECAP];
    __shared__ unsigned srt[ECAP];
    __shared__ int cnt[128];
    __shared__ int cb[128];
    __shared__ int cur[128];
    const int k = blockIdx.x, t = threadIdx.x;
    const int base = __ldg(&g_gbase[k]);
    const int ne = min(__ldg(&g_gbase[k + 1]) - base, ECAP);

    for (int i = t; i < ne; i += 256) raw[i] = __ldg(g_part + base + i);
    if (t < 128) cnt[t] = 0;
    __syncthreads();
    for (int i = t; i < ne; i += 256) atomicAdd(&cnt[raw[i] & 127], 1);
    __syncthreads();
    // exclusive scan of cnt[128]: warp 0, 4 entries per lane
    if (t < 32) {
        int c0 = cnt[t * 4], c1 = cnt[t * 4 + 1], c2 = cnt[t * 4 + 2], c3 = cnt[t * 4 + 3];
        int sl = c0 + c1 + c2 + c3;
        int p = sl;
        #pragma unroll
        for (int o = 1; o < 32; o <<= 1) {
            int x = __shfl_up_sync(0xffffffffu, p, o);
            if (t >= o) p += x;
        }
        p -= sl;
        cb[t * 4] = p;
        cb[t * 4 + 1] = p + c0;
        cb[t * 4 + 2] = p + c0 + c1;
        cb[t * 4 + 3] = p + c0 + c1 + c2;
    }
    __syncthreads();
    if (t < 128) cur[t] = cb[t];
    __syncthreads();
    for (int i = t; i < ne; i += 256) {
        unsigned r = raw[i];
        int p = atomicAdd(&cur[r & 127], 1);
        srt[p] = r >> 7;
    }
    __syncthreads();

    // gather: 8 warps x 16 local dsts
    const int w = t >> 5, lane = t & 31;
    const unsigned* embu = reinterpret_cast<const unsigned*>(g_embh);
    for (int li = w * 16; li < w * 16 + 16; li++) {
        int node = k * 128 + li;
        if (node >= n_nodes) break;
        int j = cb[li];
        int j1 = min(j + cnt[li], ne);
        unsigned acc = 0u, acc2 = 0u;   // bf16x2 zeros
        for (; j + 2 <= j1; j += 2) {
            unsigned s0 = srt[j], s1 = srt[j + 1];
            unsigned u0 = __ldg(embu + (size_t)s0 * 32 + lane);
            unsigned u1 = __ldg(embu + (size_t)s1 * 32 + lane);
            ADD_BF16X2(acc, u0);
            ADD_BF16X2(acc2, u1);
        }
        if (j < j1) {
            unsigned u = __ldg(embu + (size_t)srt[j] * 32 + lane);
            ADD_BF16X2(acc, u);
        }
        ADD_BF16X2(acc, acc2);
        reinterpret_cast<unsigned*>(g_nbr)[(size_t)node * 32 + lane] = acc;
    }
}

// ---------------------------------------------------------------------------
// K5: HMMA MLP + relu + graph-sum (proven ~2.4us, unchanged).
// ---------------------------------------------------------------------------
#define MLP_BLOCKS 592
#define RSTRIDE 272

#define LDSM_X4(r0, r1, r2, r3, addr) \
    asm volatile("ldmatrix.sync.aligned.m8n8.x4.shared.b16 {%0,%1,%2,%3}, [%4];" \
                 : "=r"(r0), "=r"(r1), "=r"(r2), "=r"(r3) : "r"(addr))

#define MMA_BF16(c0, c1, c2, c3, a0, a1, a2, a3, b0, b1) \
    asm volatile("mma.sync.aligned.m16n8k16.row.col.f32.bf16.bf16.f32 " \
                 "{%0,%1,%2,%3}, {%4,%5,%6,%7}, {%8,%9}, {%0,%1,%2,%3};" \
                 : "+f"(c0), "+f"(c1), "+f"(c2), "+f"(c3) \
                 : "r"(a0), "r"(a1), "r"(a2), "r"(a3), "r"(b0), "r"(b1))

__global__ __launch_bounds__(128) void mlp_hmma_kernel(
    const float* __restrict__ feat,
    const float* __restrict__ W1,
    const float* __restrict__ b1,
    const float* __restrict__ W2,
    const float* __restrict__ b2,
    float* __restrict__ out,
    int n_nodes) {

    __shared__ __align__(16) char As[64 * RSTRIDE];
    __shared__ __align__(16) char Bs[64 * RSTRIDE];
    __shared__ float bias[D];
    __shared__ float red[4][D];

    const int t = threadIdx.x;
    const int w = t >> 5;
    const int l = t & 31;

    for (int i = t; i < 1024; i += 128) {
        int o = i >> 4, kg = i & 15;
        float4 a = __ldg(reinterpret_cast<const float4*>(W1) + o * 16 + kg);
        float4 b = __ldg(reinterpret_cast<const float4*>(W2) + o * 16 + kg);
        uint2 pa, pb;
        pa.x = pack_bf2(a.x, a.y); pa.y = pack_bf2(a.z, a.w);
        pb.x = pack_bf2(b.x, b.y); pb.y = pack_bf2(b.z, b.w);
        *reinterpret_cast<uint2*>(Bs + o * RSTRIDE + kg * 8) = pa;
        *reinterpret_cast<uint2*>(Bs + o * RSTRIDE + 128 + kg * 8) = pb;
    }
    if (t < D) bias[t] = __ldg(b1 + t) + __ldg(b2 + t);
    __syncthreads();

    float biasr[8][2];
    #pragma unroll
    for (int f = 0; f < 8; f++) {
        int c0 = f * 8 + (l & 3) * 2;
        biasr[f][0] = bias[c0];
        biasr[f][1] = bias[c0 + 1];
    }

    float colsum[8][2];
    #pragma unroll
    for (int f = 0; f < 8; f++) { colsum[f][0] = 0.f; colsum[f][1] = 0.f; }

    const uint32_t As_u = (uint32_t)__cvta_generic_to_shared(As);
    const uint32_t Bs_u = (uint32_t)__cvta_generic_to_shared(Bs);
    const int quad = l >> 2;

    const int n_tiles = (n_nodes + 63) >> 6;
    for (int tile = blockIdx.x; tile < n_tiles; tile += gridDim.x) {
        const int base = tile << 6;
        __syncthreads();

        #pragma unroll
        for (int j = 0; j < 8; j++) {
            int idx = t + j * 128;
            int row = idx >> 4, kg = idx & 15;
            int v = base + row;
            uint2 p = make_uint2(0u, 0u);
            if (v < n_nodes) {
                float4 x = __ldg(reinterpret_cast<const float4*>(feat) + (size_t)v * 16 + kg);
                p.x = pack_bf2(x.x, x.y);
                p.y = pack_bf2(x.z, x.w);
            }
            *reinterpret_cast<uint2*>(As + row * RSTRIDE + kg * 8) = p;
        }
        #pragma unroll
        for (int j = 0; j < 4; j++) {
            int idx = t + j * 128;
            int row = idx >> 3, c = idx & 7;
            int v = base + row;
            uint4 u = (v < n_nodes)
                ? *(reinterpret_cast<const uint4*>(g_nbr) + (size_t)v * 8 + c)
                : make_uint4(0u, 0u, 0u, 0u);
            *reinterpret_cast<uint4*>(As + row * RSTRIDE + 128 + c * 16) = u;
        }
        __syncthreads();

        float acc[8][4];
        #pragma unroll
        for (int f = 0; f < 8; f++)
            #pragma unroll
            for (int q = 0; q < 4; q++) acc[f][q] = 0.f;

        #pragma unroll
        for (int s2 = 0; s2 < 4; s2++) {
            uint32_t a0[4], a1[4];
            uint32_t arow = As_u + (w * 16 + (l & 15)) * RSTRIDE + s2 * 64 + ((l >> 4) << 4);
            LDSM_X4(a0[0], a0[1], a0[2], a0[3], arow);
            LDSM_X4(a1[0], a1[1], a1[2], a1[3], arow + 32);
            #pragma unroll
            for (int f = 0; f < 8; f++) {
                uint32_t b[4];
                uint32_t baddr = Bs_u + (f * 8 + (l & 7)) * RSTRIDE + s2 * 64 + ((l >> 3) & 3) * 16;
                LDSM_X4(b[0], b[1], b[2], b[3], baddr);
                MMA_BF16(acc[f][0], acc[f][1], acc[f][2], acc[f][3],
                         a0[0], a0[1], a0[2], a0[3], b[0], b[1]);
                MMA_BF16(acc[f][0], acc[f][1], acc[f][2], acc[f][3],
                         a1[0], a1[1], a1[2], a1[3], b[2], b[3]);
            }
        }

        const bool vlo = (base + w * 16 + quad) < n_nodes;
        const bool vhi = (base + w * 16 + quad + 8) < n_nodes;
        #pragma unroll
        for (int f = 0; f < 8; f++) {
            if (vlo) {
                colsum[f][0] += fmaxf(acc[f][0] + biasr[f][0], 0.f);
                colsum[f][1] += fmaxf(acc[f][1] + biasr[f][1], 0.f);
            }
            if (vhi) {
                colsum[f][0] += fmaxf(acc[f][2] + biasr[f][0], 0.f);
                colsum[f][1] += fmaxf(acc[f][3] + biasr[f][1], 0.f);
            }
        }
    }

    #pragma unroll
    for (int f = 0; f < 8; f++) {
        #pragma unroll
        for (int j = 0; j < 2; j++) {
            float v = colsum[f][j];
            v += __shfl_xor_sync(0xffffffffu, v, 4);
            v += __shfl_xor_sync(0xffffffffu, v, 8);
            v += __shfl_xor_sync(0xffffffffu, v, 16);
            colsum[f][j] = v;
        }
    }
    if (l < 4) {
        #pragma unroll
        for (int f = 0; f < 8; f++) {
            red[w][f * 8 + l * 2 + 0] = colsum[f][0];
            red[w][f * 8 + l * 2 + 1] = colsum[f][1];
        }
    }
    __syncthreads();
    if (t < D) {
        atomicAdd(out + t, red[0][t] + red[1][t] + red[2][t] + red[3][t]);
    }
}

// ---------------------------------------------------------------------------
// launch — inputs (metadata order): feat, emb, W1, b1, W2, b2, edge_src, edge_dst
// Order: prep(0), bhist(1), bscan(2), place(3)<-ncu idx 3, sgather(4), mlp(5).
// ---------------------------------------------------------------------------
extern "C" void kernel_launch(void* const* d_in, const int* in_sizes, int n_in,
                              void* d_out, int out_size) {
    (void)n_in; (void)out_size;
    const float* feat = (const float*)d_in[0];
    const float* emb  = (const float*)d_in[1];
    const float* W1   = (const float*)d_in[2];
    const float* b1   = (const float*)d_in[3];
    const float* W2   = (const float*)d_in[4];
    const float* b2   = (const float*)d_in[5];
    const int* esrc   = (const int*)d_in[6];
    const int* edst   = (const int*)d_in[7];
    float* out        = (float*)d_out;

    const int n_nodes = in_sizes[0] / D;
    const int n_edges = in_sizes[6];
    const int nbuckets = (n_nodes + 127) >> 7;             // 782
    const int nbpart = (n_edges + EB - 1) / EB;            // 196

    // K0 prep
    {
        int n_grp = n_nodes * (D / 4);
        prep_kernel<<<(n_grp + 255) / 256, 256>>>(emb, out, n_grp);
    }
    // K1 bucket histogram
    bhist_kernel<<<nbpart, 256>>>(edst, n_edges, nbuckets);
    // K2 matrix scan (one block)
    bscan_kernel<<<1, 1024>>>(nbuckets, nbpart);
    // K3 place (smem-ranked, no global atomics) — profiled
    place_kernel<<<nbpart, 256>>>(esrc, edst, n_edges);
    // K4 per-bucket counting sort + gather
    sgather_kernel<<<nbuckets, 256>>>(n_nodes);
    // K5 HMMA MLP + graph reduce
    mlp_hmma_kernel<<<MLP_BLOCKS, 128>>>(feat, W1, b1, W2, b2, out, n_nodes);
}

// round 15
// speedup vs baseline: 6.8407x; 6.8407x over previous
#include <cuda_runtime.h>
#include <cuda_bf16.h>
#include <cstdint>

#define D 64
#define MAX_NODES 100000

// scratch (no cudaMalloc allowed): bf16 neighbor sums + bf16 copy of emb.
__device__ __align__(16) __nv_bfloat16 g_nbr[(size_t)MAX_NODES * D];
__device__ __align__(16) __nv_bfloat16 g_embh[(size_t)MAX_NODES * D];

static __device__ __forceinline__ uint32_t pack_bf2(float a, float b) {
    uint32_t r;
    asm("cvt.rn.bf16x2.f32 %0, %1, %2;" : "=r"(r) : "f"(b), "f"(a));  // lo=a, hi=b
    return r;
}

// ---------------------------------------------------------------------------
// K0 prep: emb fp32 -> bf16, zero g_nbr, zero d_out.
// Grid-stride, 4 independent float4 loads in flight per iteration.
// ---------------------------------------------------------------------------
#define PREP_BLOCKS 2048

__global__ __launch_bounds__(256) void prep_kernel(const float* __restrict__ emb,
                                                   float* __restrict__ out,
                                                   int n_grp) {
    const int tid = blockIdx.x * blockDim.x + threadIdx.x;
    const int stride = PREP_BLOCKS * 256;
    int i = tid;
    // main: 4 groups per iteration, independent loads
    for (; i + 3 * stride < n_grp; i += 4 * stride) {
        float4 v0 = __ldg(reinterpret_cast<const float4*>(emb) + i);
        float4 v1 = __ldg(reinterpret_cast<const float4*>(emb) + i + stride);
        float4 v2 = __ldg(reinterpret_cast<const float4*>(emb) + i + 2 * stride);
        float4 v3 = __ldg(reinterpret_cast<const float4*>(emb) + i + 3 * stride);
        uint2 p0, p1, p2, p3;
        p0.x = pack_bf2(v0.x, v0.y); p0.y = pack_bf2(v0.z, v0.w);
        p1.x = pack_bf2(v1.x, v1.y); p1.y = pack_bf2(v1.z, v1.w);
        p2.x = pack_bf2(v2.x, v2.y); p2.y = pack_bf2(v2.z, v2.w);
        p3.x = pack_bf2(v3.x, v3.y); p3.y = pack_bf2(v3.z, v3.w);
        reinterpret_cast<uint2*>(g_embh)[i] = p0;
        reinterpret_cast<uint2*>(g_embh)[i + stride] = p1;
        reinterpret_cast<uint2*>(g_embh)[i + 2 * stride] = p2;
        reinterpret_cast<uint2*>(g_embh)[i + 3 * stride] = p3;
        reinterpret_cast<uint2*>(g_nbr)[i] = make_uint2(0u, 0u);
        reinterpret_cast<uint2*>(g_nbr)[i + stride] = make_uint2(0u, 0u);
        reinterpret_cast<uint2*>(g_nbr)[i + 2 * stride] = make_uint2(0u, 0u);
        reinterpret_cast<uint2*>(g_nbr)[i + 3 * stride] = make_uint2(0u, 0u);
    }
    for (; i < n_grp; i += stride) {
        float4 v = __ldg(reinterpret_cast<const float4*>(emb) + i);
        uint2 pk;
        pk.x = pack_bf2(v.x, v.y);
        pk.y = pack_bf2(v.z, v.w);
        reinterpret_cast<uint2*>(g_embh)[i] = pk;
        reinterpret_cast<uint2*>(g_nbr)[i] = make_uint2(0u, 0u);
    }
    if (tid < D / 4) reinterpret_cast<float4*>(out)[tid] = make_float4(0.f, 0.f, 0.f, 0.f);
}

// ---------------------------------------------------------------------------
// K1 scatter: nbr[dst] += emb_bf16[src]  (8 lanes/edge, bf16x2 RED.128).
// Single launch, x2-unrolled independent streams. At the measured LTS cap
// (~11.7 TB/s incl. RMW) — byte-bound, structure final.
// ---------------------------------------------------------------------------
#define SCAT_BLOCKS 4736

#define RED_BF16X2(p, v) \
    asm volatile("red.global.add.noftz.v4.bf16x2 [%0], {%1,%2,%3,%4};" \
                 :: "l"(p), "r"((v).x), "r"((v).y), "r"((v).z), "r"((v).w) : "memory")

__global__ __launch_bounds__(256) void scatter_kernel(
    const int* __restrict__ src,
    const int* __restrict__ dst,
    int n_items) {
    const int stride = SCAT_BLOCKS * 256;
    int i = blockIdx.x * blockDim.x + threadIdx.x;
    for (; i + stride < n_items; i += 2 * stride) {
        const int i1 = i + stride;
        int e0 = i >> 3,  c0 = i & 7;
        int e1 = i1 >> 3, c1 = i1 & 7;
        int s0 = __ldg(src + e0);
        int d0 = __ldg(dst + e0);
        int s1 = __ldg(src + e1);
        int d1 = __ldg(dst + e1);
        uint4 v0 = *(reinterpret_cast<const uint4*>(g_embh) + (size_t)s0 * 8 + c0);
        uint4 v1 = *(reinterpret_cast<const uint4*>(g_embh) + (size_t)s1 * 8 + c1);
        RED_BF16X2(g_nbr + (size_t)d0 * D + c0 * 8, v0);
        RED_BF16X2(g_nbr + (size_t)d1 * D + c1 * 8, v1);
    }
    if (i < n_items) {
        int e = i >> 3, c = i & 7;
        int s = __ldg(src + e);
        int d = __ldg(dst + e);
        uint4 v = *(reinterpret_cast<const uint4*>(g_embh) + (size_t)s * 8 + c);
        RED_BF16X2(g_nbr + (size_t)d * D + c * 8, v);
    }
}

// ---------------------------------------------------------------------------
// K2: HMMA MLP + relu + graph-sum (proven ~2.4us, unchanged).
// ---------------------------------------------------------------------------
#define MLP_BLOCKS 592
#define RSTRIDE 272

#define LDSM_X4(r0, r1, r2, r3, addr) \
    asm volatile("ldmatrix.sync.aligned.m8n8.x4.shared.b16 {%0,%1,%2,%3}, [%4];" \
                 : "=r"(r0), "=r"(r1), "=r"(r2), "=r"(r3) : "r"(addr))

#define MMA_BF16(c0, c1, c2, c3, a0, a1, a2, a3, b0, b1) \
    asm volatile("mma.sync.aligned.m16n8k16.row.col.f32.bf16.bf16.f32 " \
                 "{%0,%1,%2,%3}, {%4,%5,%6,%7}, {%8,%9}, {%0,%1,%2,%3};" \
                 : "+f"(c0), "+f"(c1), "+f"(c2), "+f"(c3) \
                 : "r"(a0), "r"(a1), "r"(a2), "r"(a3), "r"(b0), "r"(b1))

__global__ __launch_bounds__(128) void mlp_hmma_kernel(
    const float* __restrict__ feat,
    const float* __restrict__ W1,
    const float* __restrict__ b1,
    const float* __restrict__ W2,
    const float* __restrict__ b2,
    float* __restrict__ out,
    int n_nodes) {

    __shared__ __align__(16) char As[64 * RSTRIDE];
    __shared__ __align__(16) char Bs[64 * RSTRIDE];
    __shared__ float bias[D];
    __shared__ float red[4][D];

    const int t = threadIdx.x;
    const int w = t >> 5;
    const int l = t & 31;

    for (int i = t; i < 1024; i += 128) {
        int o = i >> 4, kg = i & 15;
        float4 a = __ldg(reinterpret_cast<const float4*>(W1) + o * 16 + kg);
        float4 b = __ldg(reinterpret_cast<const float4*>(W2) + o * 16 + kg);
        uint2 pa, pb;
        pa.x = pack_bf2(a.x, a.y); pa.y = pack_bf2(a.z, a.w);
        pb.x = pack_bf2(b.x, b.y); pb.y = pack_bf2(b.z, b.w);
        *reinterpret_cast<uint2*>(Bs + o * RSTRIDE + kg * 8) = pa;
        *reinterpret_cast<uint2*>(Bs + o * RSTRIDE + 128 + kg * 8) = pb;
    }
    if (t < D) bias[t] = __ldg(b1 + t) + __ldg(b2 + t);
    __syncthreads();

    float biasr[8][2];
    #pragma unroll
    for (int f = 0; f < 8; f++) {
        int c0 = f * 8 + (l & 3) * 2;
        biasr[f][0] = bias[c0];
        biasr[f][1] = bias[c0 + 1];
    }

    float colsum[8][2];
    #pragma unroll
    for (int f = 0; f < 8; f++) { colsum[f][0] = 0.f; colsum[f][1] = 0.f; }

    const uint32_t As_u = (uint32_t)__cvta_generic_to_shared(As);
    const uint32_t Bs_u = (uint32_t)__cvta_generic_to_shared(Bs);
    const int quad = l >> 2;

    const int n_tiles = (n_nodes + 63) >> 6;
    for (int tile = blockIdx.x; tile < n_tiles; tile += gridDim.x) {
        const int base = tile << 6;
        __syncthreads();

        #pragma unroll
        for (int j = 0; j < 8; j++) {
            int idx = t + j * 128;
            int row = idx >> 4, kg = idx & 15;
            int v = base + row;
            uint2 p = make_uint2(0u, 0u);
            if (v < n_nodes) {
                float4 x = __ldg(reinterpret_cast<const float4*>(feat) + (size_t)v * 16 + kg);
                p.x = pack_bf2(x.x, x.y);
                p.y = pack_bf2(x.z, x.w);
            }
            *reinterpret_cast<uint2*>(As + row * RSTRIDE + kg * 8) = p;
        }
        #pragma unroll
        for (int j = 0; j < 4; j++) {
            int idx = t + j * 128;
            int row = idx >> 3, c = idx & 7;
            int v = base + row;
            uint4 u = (v < n_nodes)
                ? *(reinterpret_cast<const uint4*>(g_nbr) + (size_t)v * 8 + c)
                : make_uint4(0u, 0u, 0u, 0u);
            *reinterpret_cast<uint4*>(As + row * RSTRIDE + 128 + c * 16) = u;
        }
        __syncthreads();

        float acc[8][4];
        #pragma unroll
        for (int f = 0; f < 8; f++)
            #pragma unroll
            for (int q = 0; q < 4; q++) acc[f][q] = 0.f;

        #pragma unroll
        for (int s2 = 0; s2 < 4; s2++) {
            uint32_t a0[4], a1[4];
            uint32_t arow = As_u + (w * 16 + (l & 15)) * RSTRIDE + s2 * 64 + ((l >> 4) << 4);
            LDSM_X4(a0[0], a0[1], a0[2], a0[3], arow);
            LDSM_X4(a1[0], a1[1], a1[2], a1[3], arow + 32);
            #pragma unroll
            for (int f = 0; f < 8; f++) {
                uint32_t b[4];
                uint32_t baddr = Bs_u + (f * 8 + (l & 7)) * RSTRIDE + s2 * 64 + ((l >> 3) & 3) * 16;
                LDSM_X4(b[0], b[1], b[2], b[3], baddr);
                MMA_BF16(acc[f][0], acc[f][1], acc[f][2], acc[f][3],
                         a0[0], a0[1], a0[2], a0[3], b[0], b[1]);
                MMA_BF16(acc[f][0], acc[f][1], acc[f][2], acc[f][3],
                         a1[0], a1[1], a1[2], a1[3], b[2], b[3]);
            }
        }

        const bool vlo = (base + w * 16 + quad) < n_nodes;
        const bool vhi = (base + w * 16 + quad + 8) < n_nodes;
        #pragma unroll
        for (int f = 0; f < 8; f++) {
            if (vlo) {
                colsum[f][0] += fmaxf(acc[f][0] + biasr[f][0], 0.f);
                colsum[f][1] += fmaxf(acc[f][1] + biasr[f][1], 0.f);
            }
            if (vhi) {
                colsum[f][0] += fmaxf(acc[f][2] + biasr[f][0], 0.f);
                colsum[f][1] += fmaxf(acc[f][3] + biasr[f][1], 0.f);
            }
        }
    }

    #pragma unroll
    for (int f = 0; f < 8; f++) {
        #pragma unroll
        for (int j = 0; j < 2; j++) {
            float v = colsum[f][j];
            v += __shfl_xor_sync(0xffffffffu, v, 4);
            v += __shfl_xor_sync(0xffffffffu, v, 8);
            v += __shfl_xor_sync(0xffffffffu, v, 16);
            colsum[f][j] = v;
        }
    }
    if (l < 4) {
        #pragma unroll
        for (int f = 0; f < 8; f++) {
            red[w][f * 8 + l * 2 + 0] = colsum[f][0];
            red[w][f * 8 + l * 2 + 1] = colsum[f][1];
        }
    }
    __syncthreads();
    if (t < D) {
        atomicAdd(out + t, red[0][t] + red[1][t] + red[2][t] + red[3][t]);
    }
}

// ---------------------------------------------------------------------------
// launch — inputs (metadata order): feat, emb, W1, b1, W2, b2, edge_src, edge_dst
// 3 launches/call: prep(0), scatter(1), mlp(2). Absolute launch #3 =
// call 2's prep -> ncu profiles the improved prep.
// ---------------------------------------------------------------------------
extern "C" void kernel_launch(void* const* d_in, const int* in_sizes, int n_in,
                              void* d_out, int out_size) {
    (void)n_in; (void)out_size;
    const float* feat = (const float*)d_in[0];
    const float* emb  = (const float*)d_in[1];
    const float* W1   = (const float*)d_in[2];
    const float* b1   = (const float*)d_in[3];
    const float* W2   = (const float*)d_in[4];
    const float* b2   = (const float*)d_in[5];
    const int* esrc   = (const int*)d_in[6];
    const int* edst   = (const int*)d_in[7];
    float* out        = (float*)d_out;

    const int n_nodes = in_sizes[0] / D;
    const int n_edges = in_sizes[6];

    // K0 prep (4-way ILP grid-stride)
    prep_kernel<<<PREP_BLOCKS, 256>>>(emb, out, n_nodes * (D / 4));
    // K1 scatter (single launch)
    scatter_kernel<<<SCAT_BLOCKS, 256>>>(esrc, edst, n_edges * 8);
    // K2 HMMA MLP + graph reduce
    mlp_hmma_kernel<<<MLP_BLOCKS, 128>>>(feat, W1, b1, W2, b2, out, n_nodes);
}